// round 9
// baseline (speedup 1.0000x reference)
#include <cuda_runtime.h>
#include <math.h>

// ---------------- problem constants ----------------
#define NTOK      8192            // B*S = 4*2048
#define D_MODEL   1024
#define N_EXPERTS 8
#define N_FEAT    16
#define RAW_FEAT  512
#define PROJ_DIM  256
#define R_IN      1280
#define R_HID     256
#define E_HID     256

// output layout (floats) : next_hidden | stage_out | gate | scaled_logits | group | rule
#define OFF_STAGE 8388608ull
#define OFF_GATE  16777216ull
#define OFF_SLOG  16842752ull
#define OFF_GRP   16908288ull
#define OFF_RULE  16941056ull

// ---------------- device scratch (no allocations allowed) ----------------
__device__ float g_hnorm[(size_t)NTOK * D_MODEL];
__device__ float g_P1   [(size_t)NTOK * PROJ_DIM];
__device__ float g_P2   [(size_t)NTOK * PROJ_DIM];
__device__ float g_RHs  [(size_t)NTOK * R_HID];
__device__ float g_H1   [(size_t)N_EXPERTS * NTOK * E_HID];
__device__ int   g_tok  [N_EXPERTS * NTOK];
__device__ float g_wt   [N_EXPERTS * NTOK];
__device__ int   g_cnt  [N_EXPERTS];

// ---------------- helpers ----------------
__device__ __forceinline__ float gelu_tanh(float x) {
    float x3 = x * x * x;
    return 0.5f * x * (1.0f + tanhf(0.7978845608028654f * (x + 0.044715f * x3)));
}

// ================= K1: layernorm + init =================
__global__ __launch_bounds__(256) void k_layernorm(
    const float* __restrict__ hidden,
    const float* __restrict__ ln_g,
    const float* __restrict__ ln_b,
    float* __restrict__ out)
{
    int t   = blockIdx.x;
    int tid = threadIdx.x;
    const float* x = hidden + (size_t)t * D_MODEL;

    float v[4], s = 0.f, s2 = 0.f;
#pragma unroll
    for (int j = 0; j < 4; j++) {
        v[j] = x[tid + 256 * j];
        s  += v[j];
        s2 += v[j] * v[j];
    }
#pragma unroll
    for (int o = 16; o; o >>= 1) {
        s  += __shfl_down_sync(0xffffffffu, s,  o);
        s2 += __shfl_down_sync(0xffffffffu, s2, o);
    }
    __shared__ float ps[8], ps2[8];
    __shared__ float mu_s, rs_s;
    int w = tid >> 5, l = tid & 31;
    if (l == 0) { ps[w] = s; ps2[w] = s2; }
    __syncthreads();
    if (tid == 0) {
        float S = 0.f, S2 = 0.f;
#pragma unroll
        for (int i = 0; i < 8; i++) { S += ps[i]; S2 += ps2[i]; }
        float mu  = S * (1.0f / D_MODEL);
        float var = S2 * (1.0f / D_MODEL) - mu * mu;
        mu_s = mu;
        rs_s = rsqrtf(var + 1e-5f);
    }
    __syncthreads();
    float mu = mu_s, rs = rs_s;
#pragma unroll
    for (int j = 0; j < 4; j++) {
        int d = tid + 256 * j;
        float hn = (v[j] - mu) * rs * ln_g[d] + ln_b[d];
        g_hnorm[(size_t)t * D_MODEL + d] = hn;
        out[OFF_STAGE + (size_t)t * D_MODEL + d] = 0.0f;
    }
    if (t == 0 && tid < N_EXPERTS) g_cnt[tid] = 0;
}

// ================= 128x64x8 double-buffered SGEMM, 8x8 microtile, 128 threads =================
// MODE 0: plain C = act(A@B + bias)
// MODE 1: expert GEMM1 (gathered A rows via g_tok), C = gelu(...) compacted
// MODE 2: expert GEMM2, gate-weighted atomicAdd scatter into stage_out
// MODE 3: concat-A (A for k<ksplit, A2 for k>=ksplit)
template<int MODE, int ACT>
__global__ __launch_bounds__(128, 4) void gemm_t(
    const float* __restrict__ A,  int lda,
    const float* __restrict__ A2, int lda2, int ksplit,
    const float* __restrict__ B,  int ldb,
    const float* __restrict__ bias,
    float* __restrict__ C, int ldc, int K, int Mfull)
{
    __shared__ float As[2][8][128];
    __shared__ float Bs[2][8][64];
    __shared__ int   tok_s[128];
    __shared__ float wt_s[128];

    const int t  = threadIdx.x;
    const int m0 = blockIdx.x * 128;
    const int n0 = blockIdx.y * 64;
    const int e  = blockIdx.z;

    int M = Mfull;
    if (MODE == 1 || MODE == 2) {
        M = g_cnt[e];
        if (m0 >= M) return;
        B    += (size_t)e * K * ldb;
        bias += (size_t)e * ldc;
        if (MODE == 1) C += (size_t)e * NTOK * ldc;
        if (MODE == 2) A += (size_t)e * NTOK * lda;
        int idx = e * NTOK + min(m0 + t, M - 1);
        tok_s[t] = g_tok[idx];
        if (MODE == 2) wt_s[t] = g_wt[idx];
        __syncthreads();
    }

    // per-thread roles
    const int arow = t;                       // A: one row, 8 k's (2 x float4)
    const int bkr  = t >> 4, bnc = (t & 15) * 4;  // B: one float4
    const int ty = t >> 3, tx = t & 7;        // compute: 16x8 thread grid

    size_t rowi;
    if (MODE == 1)      rowi = (size_t)tok_s[arow];
    else if (MODE == 2) rowi = (size_t)min(m0 + arow, M - 1);
    else                rowi = (size_t)(m0 + arow);
    const float* Abase  = A + rowi * lda;
    const float* A2base = (MODE == 3) ? (A2 + rowi * lda2) : A;

    const float* Bbase = B + (size_t)bkr * ldb + n0 + bnc;

#define LOAD_A(K0, V0, V1) do {                                              \
        const float* _p = (MODE == 3 && (K0) >= ksplit)                      \
                        ? (A2base + ((K0) - ksplit)) : (Abase + (K0));       \
        V0 = *reinterpret_cast<const float4*>(_p);                           \
        V1 = *reinterpret_cast<const float4*>(_p + 4);                       \
    } while (0)

#define STORE_A(BUF, V0, V1) do {                                            \
        As[BUF][0][arow] = V0.x; As[BUF][1][arow] = V0.y;                    \
        As[BUF][2][arow] = V0.z; As[BUF][3][arow] = V0.w;                    \
        As[BUF][4][arow] = V1.x; As[BUF][5][arow] = V1.y;                    \
        As[BUF][6][arow] = V1.z; As[BUF][7][arow] = V1.w;                    \
    } while (0)

    // preload tile 0
    {
        float4 a0, a1;
        LOAD_A(0, a0, a1);
        float4 b0 = *reinterpret_cast<const float4*>(Bbase);
        STORE_A(0, a0, a1);
        *reinterpret_cast<float4*>(&Bs[0][bkr][bnc]) = b0;
    }
    __syncthreads();

    float acc[8][8];
#pragma unroll
    for (int i = 0; i < 8; i++)
#pragma unroll
        for (int j = 0; j < 8; j++) acc[i][j] = 0.f;

    int buf = 0;
    for (int k0 = 8; k0 < K; k0 += 8) {
        float4 na0, na1;
        LOAD_A(k0, na0, na1);
        float4 nb0 = *reinterpret_cast<const float4*>(Bbase + (size_t)k0 * ldb);
#pragma unroll
        for (int kk = 0; kk < 8; kk++) {
            float a[8], b[8];
            *reinterpret_cast<float4*>(&a[0]) = *reinterpret_cast<const float4*>(&As[buf][kk][ty * 4]);
            *reinterpret_cast<float4*>(&a[4]) = *reinterpret_cast<const float4*>(&As[buf][kk][ty * 4 + 64]);
            *reinterpret_cast<float4*>(&b[0]) = *reinterpret_cast<const float4*>(&Bs[buf][kk][tx * 4]);
            *reinterpret_cast<float4*>(&b[4]) = *reinterpret_cast<const float4*>(&Bs[buf][kk][tx * 4 + 32]);
#pragma unroll
            for (int i = 0; i < 8; i++)
#pragma unroll
                for (int j = 0; j < 8; j++)
                    acc[i][j] = fmaf(a[i], b[j], acc[i][j]);
        }
        int nb = buf ^ 1;
        STORE_A(nb, na0, na1);
        *reinterpret_cast<float4*>(&Bs[nb][bkr][bnc]) = nb0;
        __syncthreads();
        buf = nb;
    }
#pragma unroll
    for (int kk = 0; kk < 8; kk++) {
        float a[8], b[8];
        *reinterpret_cast<float4*>(&a[0]) = *reinterpret_cast<const float4*>(&As[buf][kk][ty * 4]);
        *reinterpret_cast<float4*>(&a[4]) = *reinterpret_cast<const float4*>(&As[buf][kk][ty * 4 + 64]);
        *reinterpret_cast<float4*>(&b[0]) = *reinterpret_cast<const float4*>(&Bs[buf][kk][tx * 4]);
        *reinterpret_cast<float4*>(&b[4]) = *reinterpret_cast<const float4*>(&Bs[buf][kk][tx * 4 + 32]);
#pragma unroll
        for (int i = 0; i < 8; i++)
#pragma unroll
            for (int j = 0; j < 8; j++)
                acc[i][j] = fmaf(a[i], b[j], acc[i][j]);
    }

    // epilogue
    float bb[8];
#pragma unroll
    for (int j = 0; j < 4; j++) {
        bb[j]     = bias[n0 + tx * 4 + j];
        bb[4 + j] = bias[n0 + 32 + tx * 4 + j];
    }

#pragma unroll
    for (int ih = 0; ih < 2; ih++) {
#pragma unroll
        for (int i = 0; i < 4; i++) {
            int rl = ih * 64 + ty * 4 + i;
            int ri = ih * 4 + i;
            int m  = m0 + rl;
            if (MODE == 0 || MODE == 3) {
                float4 v0, v1;
                float* p0 = &v0.x;
                float* p1 = &v1.x;
#pragma unroll
                for (int j = 0; j < 4; j++) {
                    float x0 = acc[ri][j]     + bb[j];
                    float x1 = acc[ri][4 + j] + bb[4 + j];
                    if (ACT) { x0 = gelu_tanh(x0); x1 = gelu_tanh(x1); }
                    p0[j] = x0; p1[j] = x1;
                }
                *reinterpret_cast<float4*>(&C[(size_t)m * ldc + n0 + tx * 4])      = v0;
                *reinterpret_cast<float4*>(&C[(size_t)m * ldc + n0 + 32 + tx * 4]) = v1;
            } else if (MODE == 1) {
                if (m < M) {
                    float4 v0, v1;
                    float* p0 = &v0.x;
                    float* p1 = &v1.x;
#pragma unroll
                    for (int j = 0; j < 4; j++) {
                        p0[j] = gelu_tanh(acc[ri][j]     + bb[j]);
                        p1[j] = gelu_tanh(acc[ri][4 + j] + bb[4 + j]);
                    }
                    *reinterpret_cast<float4*>(&C[(size_t)m * ldc + n0 + tx * 4])      = v0;
                    *reinterpret_cast<float4*>(&C[(size_t)m * ldc + n0 + 32 + tx * 4]) = v1;
                }
            } else {  // MODE == 2
                if (m < M) {
                    int   tok = tok_s[rl];
                    float wgt = wt_s[rl];
                    float* dst = C + (size_t)tok * ldc + n0;
#pragma unroll
                    for (int j = 0; j < 4; j++) {
                        atomicAdd(&dst[tx * 4 + j],      (acc[ri][j]     + bb[j])     * wgt);
                        atomicAdd(&dst[32 + tx * 4 + j], (acc[ri][4 + j] + bb[4 + j]) * wgt);
                    }
                }
            }
        }
    }
#undef LOAD_A
#undef STORE_A
}

// ================= K5: router logits, top-2 softmax, small outputs, dispatch =================
__global__ __launch_bounds__(256) void k_router(
    const float* __restrict__ r_w2, const float* __restrict__ r_b2,
    const float* __restrict__ feat,
    const float* __restrict__ rr_w, const float* __restrict__ rr_b,
    float* __restrict__ out)
{
    int w = threadIdx.x >> 5, l = threadIdx.x & 31;
    int t = blockIdx.x * 8 + w;
    const float* rh = g_RHs + (size_t)t * R_HID;

    float acc[8] = {};
    for (int k = l; k < R_HID; k += 32) {
        float v = rh[k];
#pragma unroll
        for (int e = 0; e < 8; e++) acc[e] = fmaf(v, r_w2[k * 8 + e], acc[e]);
    }
#pragma unroll
    for (int o = 16; o; o >>= 1)
#pragma unroll
        for (int e = 0; e < 8; e++) acc[e] += __shfl_down_sync(0xffffffffu, acc[e], o);

    if (l == 0) {
        float lg[8];
#pragma unroll
        for (int e = 0; e < 8; e++) lg[e] = acc[e] + r_b2[e];
        int i1 = 0; float m1 = lg[0];
#pragma unroll
        for (int e = 1; e < 8; e++) if (lg[e] > m1) { m1 = lg[e]; i1 = e; }
        float m2 = -3.4e38f;
#pragma unroll
        for (int e = 0; e < 8; e++) if (e != i1 && lg[e] > m2) m2 = lg[e];
        float Z = 0.f, g[8];
#pragma unroll
        for (int e = 0; e < 8; e++) {
            if (lg[e] >= m2) { g[e] = expf(lg[e] - m1); Z += g[e]; }
            else g[e] = 0.f;
        }
        float invZ = 1.0f / Z;
#pragma unroll
        for (int e = 0; e < 8; e++) {
            g[e] *= invZ;
            out[OFF_GATE + (size_t)t * 8 + e] = g[e];
            out[OFF_SLOG + (size_t)t * 8 + e] = lg[e];
        }
#pragma unroll
        for (int gi = 0; gi < 4; gi++)
            out[OFF_GRP + (size_t)t * 4 + gi] = g[2 * gi] + g[2 * gi + 1];
        float fv[16];
#pragma unroll
        for (int i = 0; i < 16; i++) fv[i] = feat[(size_t)t * 16 + i];
#pragma unroll
        for (int e = 0; e < 8; e++) {
            float r = rr_b[e];
#pragma unroll
            for (int i = 0; i < 16; i++) r = fmaf(fv[i], rr_w[i * 8 + e], r);
            out[OFF_RULE + (size_t)t * 8 + e] = r;
        }
#pragma unroll
        for (int e = 0; e < 8; e++) {
            if (g[e] > 0.f) {
                int p = atomicAdd(&g_cnt[e], 1);
                g_tok[e * NTOK + p] = t;
                g_wt [e * NTOK + p] = g[e];
            }
        }
    }
}

// ================= K8: next_hidden = hidden + alpha * stage_out =================
__global__ __launch_bounds__(256) void k_finalize(
    const float* __restrict__ hidden,
    const float* __restrict__ alpha,
    float* __restrict__ out)
{
    size_t i = ((size_t)blockIdx.x * 256 + threadIdx.x) * 4;
    float a = alpha[0];
    float4 h = *reinterpret_cast<const float4*>(hidden + i);
    float4 s = *reinterpret_cast<const float4*>(out + OFF_STAGE + i);
    float4 r;
    r.x = h.x + a * s.x;
    r.y = h.y + a * s.y;
    r.z = h.z + a * s.z;
    r.w = h.w + a * s.w;
    *reinterpret_cast<float4*>(out + i) = r;
}

// ================= host launcher =================
extern "C" void kernel_launch(void* const* d_in, const int* in_sizes, int n_in,
                              void* d_out, int out_size)
{
    const float* hidden = (const float*)d_in[0];
    const float* feat   = (const float*)d_in[1];
    const float* bank   = (const float*)d_in[2];
    // d_in[3] = item_seq_len (unused by reference outputs)
    const float* ln_g   = (const float*)d_in[4];
    const float* ln_b   = (const float*)d_in[5];
    const float* fp_w1  = (const float*)d_in[6];
    const float* fp_b1  = (const float*)d_in[7];
    const float* fp_w2  = (const float*)d_in[8];
    const float* fp_b2  = (const float*)d_in[9];
    const float* r_w1   = (const float*)d_in[10];
    const float* r_b1   = (const float*)d_in[11];
    const float* r_w2   = (const float*)d_in[12];
    const float* r_b2   = (const float*)d_in[13];
    const float* rr_w   = (const float*)d_in[14];
    const float* rr_b   = (const float*)d_in[15];
    const float* e_w1   = (const float*)d_in[16];
    const float* e_b1   = (const float*)d_in[17];
    const float* e_w2   = (const float*)d_in[18];
    const float* e_b2   = (const float*)d_in[19];
    const float* alpha  = (const float*)d_in[20];
    float* out = (float*)d_out;

    float *p_P1, *p_P2, *p_RHs, *p_hn, *p_H1;
    cudaGetSymbolAddress((void**)&p_P1,  g_P1);
    cudaGetSymbolAddress((void**)&p_P2,  g_P2);
    cudaGetSymbolAddress((void**)&p_RHs, g_RHs);
    cudaGetSymbolAddress((void**)&p_hn,  g_hnorm);
    cudaGetSymbolAddress((void**)&p_H1,  g_H1);

    // K1: layernorm -> g_hnorm, zero stage_out, reset counters
    k_layernorm<<<NTOK, 256>>>(hidden, ln_g, ln_b, out);

    // K2: P1 = gelu(bank @ fp_w1 + fp_b1)   [8192x512 @ 512x256], grid 256
    gemm_t<0, 1><<<dim3(NTOK / 128, PROJ_DIM / 64), 128>>>(
        bank, RAW_FEAT, nullptr, 0, 0, fp_w1, PROJ_DIM, fp_b1,
        p_P1, PROJ_DIM, RAW_FEAT, NTOK);

    // K3: P2 = P1 @ fp_w2 + fp_b2           [8192x256 @ 256x256], grid 256
    gemm_t<0, 0><<<dim3(NTOK / 128, PROJ_DIM / 64), 128>>>(
        p_P1, PROJ_DIM, nullptr, 0, 0, fp_w2, PROJ_DIM, fp_b2,
        p_P2, PROJ_DIM, PROJ_DIM, NTOK);

    // K4: RH = gelu(concat(hnorm,P2) @ r_w1 + r_b1)  [8192x1280 @ 1280x256], grid 256
    gemm_t<3, 1><<<dim3(NTOK / 128, R_HID / 64), 128>>>(
        p_hn, D_MODEL, p_P2, PROJ_DIM, D_MODEL, r_w1, R_HID, r_b1,
        p_RHs, R_HID, R_IN, NTOK);

    // K5: logits, top-2 softmax, small outputs, expert dispatch
    k_router<<<NTOK / 8, 256>>>(r_w2, r_b2, feat, rr_w, rr_b, out);

    // K6: per-expert gathered GEMM1 (gelu) -> g_H1, ~512 active CTAs
    gemm_t<1, 1><<<dim3(NTOK / 128, E_HID / 64, N_EXPERTS), 128>>>(
        p_hn, D_MODEL, nullptr, 0, 0, e_w1, E_HID, e_b1,
        p_H1, E_HID, D_MODEL, 0);

    // K7: per-expert GEMM2, gate-weighted atomic accumulate, ~2048 active CTAs
    gemm_t<2, 0><<<dim3(NTOK / 128, D_MODEL / 64, N_EXPERTS), 128>>>(
        p_H1, E_HID, nullptr, 0, 0, e_w2, D_MODEL, e_b2,
        out + OFF_STAGE, D_MODEL, E_HID, 0);

    // K8: next_hidden = hidden + alpha * stage_out
    k_finalize<<<(NTOK * D_MODEL) / (256 * 4), 256>>>(hidden, alpha, out);
}